// round 4
// baseline (speedup 1.0000x reference)
#include <cuda_runtime.h>

// spu(z) = z^2 - 0.5 (z>=0), sigmoid(-z) - 1 (z<0); dspu analogous.
// Elementwise over d = 16,777,216 fp32; 192 MiB in + 192 MiB out -> pure HBM stream.
// R2: 8 floats/thread (2x float4, loads front-batched -> MLP_p1=6), streaming
// cache hints (__ldcs/__stcs) since nothing is re-used.

__device__ __forceinline__ float sigm_neg(float z) {
    return __fdividef(1.0f, 1.0f + __expf(z));
}

__device__ __forceinline__ float spu_f(float z) {
    float s = sigm_neg(z);
    return (z >= 0.0f) ? fmaf(z, z, -0.5f) : (s - 1.0f);
}

__device__ __forceinline__ void spu_elem(float x, float l, float u,
                                         float& xo, float& lo, float& uo) {
    float p = u - 0.5f * (fabsf(l) + fabsf(u));
    p = fminf(fmaxf(p, l), u);

    float sl = spu_f(l);
    float su = spu_f(u);
    float ps = sigm_neg(p);
    float sp        = (p >= 0.0f) ? fmaf(p, p, -0.5f) : (ps - 1.0f);
    float tan_slope = (p >= 0.0f) ? (2.0f * p) : (-ps * (1.0f - ps));
    float tan_int   = sp - p * tan_slope;

    float du = (u != l) ? (u - l) : 1.0f;
    float chord_slope = __fdividef(su - sl, du);
    float chord_int   = sl - chord_slope * l;

    float dl = (l != 0.0f) ? (-l) : 1.0f;
    float zl_slope = __fdividef(-0.5f - sl, dl);

    bool upos = (u > 0.0f);
    bool ppos = (p >= 0.0f);

    float lb_slope = upos ? (ppos ? tan_slope : zl_slope) : chord_slope;
    float lb_int   = upos ? (ppos ? tan_int   : -0.5f   ) : chord_int;
    float ub_slope = upos ? chord_slope : tan_slope;
    float ub_int   = upos ? chord_int   : tan_int;

    lo = fmaf((lb_slope > 0.0f) ? l : u, lb_slope, lb_int);
    uo = fmaf((ub_slope > 0.0f) ? u : l, ub_slope, ub_int);
    xo = spu_f(x);
}

__device__ __forceinline__ void spu_vec4(const float4& xv, const float4& lv,
                                         const float4& uv, float4& xo,
                                         float4& lo, float4& uo) {
    spu_elem(xv.x, lv.x, uv.x, xo.x, lo.x, uo.x);
    spu_elem(xv.y, lv.y, uv.y, xo.y, lo.y, uo.y);
    spu_elem(xv.z, lv.z, uv.z, xo.z, lo.z, uo.z);
    spu_elem(xv.w, lv.w, uv.w, xo.w, lo.w, uo.w);
}

__global__ __launch_bounds__(256)
void spu_transformer_kernel(const float4* __restrict__ x,
                            const float4* __restrict__ l,
                            const float4* __restrict__ u,
                            float4* __restrict__ x_out,
                            float4* __restrict__ l_out,
                            float4* __restrict__ u_out,
                            int n4) {
    // 2 float4 per thread, consecutive (warp still fully coalesced: pair-stride 2)
    int i0 = (blockIdx.x * blockDim.x + threadIdx.x) * 2;
    if (i0 >= n4) return;
    int i1 = i0 + 1;

    // Front-batch all 6 loads (MLP_p1 = 6), evict-first
    float4 xv0 = __ldcs(x + i0);
    float4 xv1 = __ldcs(x + i1);
    float4 lv0 = __ldcs(l + i0);
    float4 lv1 = __ldcs(l + i1);
    float4 uv0 = __ldcs(u + i0);
    float4 uv1 = __ldcs(u + i1);

    float4 xo0, lo0, uo0, xo1, lo1, uo1;
    spu_vec4(xv0, lv0, uv0, xo0, lo0, uo0);
    spu_vec4(xv1, lv1, uv1, xo1, lo1, uo1);

    __stcs(x_out + i0, xo0);
    __stcs(x_out + i1, xo1);
    __stcs(l_out + i0, lo0);
    __stcs(l_out + i1, lo1);
    __stcs(u_out + i0, uo0);
    __stcs(u_out + i1, uo1);
}

extern "C" void kernel_launch(void* const* d_in, const int* in_sizes, int n_in,
                              void* d_out, int out_size) {
    const float* x = (const float*)d_in[0];
    const float* l = (const float*)d_in[1];
    const float* u = (const float*)d_in[2];
    float* out = (float*)d_out;

    int n = in_sizes[0];            // 16,777,216 (divisible by 8)
    int n4 = n >> 2;

    float* x_out = out;
    float* l_out = out + (size_t)n;
    float* u_out = out + 2 * (size_t)n;

    int threads = 256;
    int elems_per_block = threads * 2;          // in float4 units
    int blocks = (n4 + elems_per_block - 1) / elems_per_block;   // 4096
    spu_transformer_kernel<<<blocks, threads>>>(
        (const float4*)x, (const float4*)l, (const float4*)u,
        (float4*)x_out, (float4*)l_out, (float4*)u_out, n4);
}

// round 5
// speedup vs baseline: 1.0010x; 1.0010x over previous
#include <cuda_runtime.h>

// spu(z) = z^2 - 0.5 (z>=0), sigmoid(-z) - 1 (z<0); dspu analogous.
// Elementwise over d = 16,777,216 fp32; 192 MiB in + 192 MiB out -> pure HBM stream.
// R4: 8 floats/thread via BLOCK-STRIDED 2x float4 unroll (thread t -> t and t+256),
// so every LDG.128/STG.128 is fully coalesced (128B line per warp per instruction),
// with all 6 loads front-batched (MLP_p1 = 6).

__device__ __forceinline__ float sigm_neg(float z) {
    return __fdividef(1.0f, 1.0f + __expf(z));
}

__device__ __forceinline__ float spu_f(float z) {
    float s = sigm_neg(z);
    return (z >= 0.0f) ? fmaf(z, z, -0.5f) : (s - 1.0f);
}

__device__ __forceinline__ void spu_elem(float x, float l, float u,
                                         float& xo, float& lo, float& uo) {
    float p = u - 0.5f * (fabsf(l) + fabsf(u));
    p = fminf(fmaxf(p, l), u);

    float sl = spu_f(l);
    float su = spu_f(u);
    float ps = sigm_neg(p);
    float sp        = (p >= 0.0f) ? fmaf(p, p, -0.5f) : (ps - 1.0f);
    float tan_slope = (p >= 0.0f) ? (2.0f * p) : (-ps * (1.0f - ps));
    float tan_int   = sp - p * tan_slope;

    float du = (u != l) ? (u - l) : 1.0f;
    float chord_slope = __fdividef(su - sl, du);
    float chord_int   = sl - chord_slope * l;

    float dl = (l != 0.0f) ? (-l) : 1.0f;
    float zl_slope = __fdividef(-0.5f - sl, dl);

    bool upos = (u > 0.0f);
    bool ppos = (p >= 0.0f);

    float lb_slope = upos ? (ppos ? tan_slope : zl_slope) : chord_slope;
    float lb_int   = upos ? (ppos ? tan_int   : -0.5f   ) : chord_int;
    float ub_slope = upos ? chord_slope : tan_slope;
    float ub_int   = upos ? chord_int   : tan_int;

    lo = fmaf((lb_slope > 0.0f) ? l : u, lb_slope, lb_int);
    uo = fmaf((ub_slope > 0.0f) ? u : l, ub_slope, ub_int);
    xo = spu_f(x);
}

__device__ __forceinline__ void spu_vec4(const float4& xv, const float4& lv,
                                         const float4& uv, float4& xo,
                                         float4& lo, float4& uo) {
    spu_elem(xv.x, lv.x, uv.x, xo.x, lo.x, uo.x);
    spu_elem(xv.y, lv.y, uv.y, xo.y, lo.y, uo.y);
    spu_elem(xv.z, lv.z, uv.z, xo.z, lo.z, uo.z);
    spu_elem(xv.w, lv.w, uv.w, xo.w, lo.w, uo.w);
}

__global__ __launch_bounds__(256)
void spu_transformer_kernel(const float4* __restrict__ x,
                            const float4* __restrict__ l,
                            const float4* __restrict__ u,
                            float4* __restrict__ x_out,
                            float4* __restrict__ l_out,
                            float4* __restrict__ u_out) {
    // Block handles 512 contiguous float4s; thread t takes t and t+256.
    // Every memory instruction is a fully-coalesced 128B-per-warp access.
    int base = blockIdx.x * 512 + threadIdx.x;
    int i0 = base;
    int i1 = base + 256;

    // Front-batch all 6 loads (MLP_p1 = 6), all coalesced.
    float4 xv0 = x[i0];
    float4 xv1 = x[i1];
    float4 lv0 = l[i0];
    float4 lv1 = l[i1];
    float4 uv0 = u[i0];
    float4 uv1 = u[i1];

    float4 xo0, lo0, uo0, xo1, lo1, uo1;
    spu_vec4(xv0, lv0, uv0, xo0, lo0, uo0);
    spu_vec4(xv1, lv1, uv1, xo1, lo1, uo1);

    x_out[i0] = xo0;
    x_out[i1] = xo1;
    l_out[i0] = lo0;
    l_out[i1] = lo1;
    u_out[i0] = uo0;
    u_out[i1] = uo1;
}

extern "C" void kernel_launch(void* const* d_in, const int* in_sizes, int n_in,
                              void* d_out, int out_size) {
    const float* x = (const float*)d_in[0];
    const float* l = (const float*)d_in[1];
    const float* u = (const float*)d_in[2];
    float* out = (float*)d_out;

    int n = in_sizes[0];            // 16,777,216 (divisible by 2048)
    int n4 = n >> 2;                // 4,194,304 float4s

    float* x_out = out;
    float* l_out = out + (size_t)n;
    float* u_out = out + 2 * (size_t)n;

    int threads = 256;
    int blocks = n4 / 512;          // 8192, exact
    spu_transformer_kernel<<<blocks, threads>>>(
        (const float4*)x, (const float4*)l, (const float4*)u,
        (float4*)x_out, (float4*)l_out, (float4*)u_out);
}

// round 6
// speedup vs baseline: 1.0486x; 1.0475x over previous
#include <cuda_runtime.h>

// spu(z) = z^2 - 0.5 (z>=0), sigmoid(-z) - 1 (z<0); dspu analogous.
// Elementwise over d = 16,777,216 fp32; 192 MiB in + 192 MiB out -> HBM stream.
// R5 = R1 memory layout (1 float4/thread, fully coalesced, 32 regs, occ 86%)
//      + instruction thinning: sigmoid via single-MUFU tanh.approx:
//        sigmoid(-z) = 0.5 - 0.5*tanh(z/2)
//        s - 1       = -0.5 - 0.5*t
//        -s*(1-s)    = 0.25*t^2 - 0.25        (t = tanh(z/2))

__device__ __forceinline__ float tanh_half(float z) {
    float t;
    asm("tanh.approx.f32 %0, %1;" : "=f"(t) : "f"(0.5f * z));
    return t;
}

// spu(z) using one MUFU: t = tanh(z/2); neg branch value = -0.5 - 0.5 t
__device__ __forceinline__ float spu_f(float z) {
    float t = tanh_half(z);
    float neg = fmaf(-0.5f, t, -0.5f);       // sigmoid(-z) - 1
    float pos = fmaf(z, z, -0.5f);
    return (z >= 0.0f) ? pos : neg;
}

__device__ __forceinline__ void spu_elem(float x, float l, float u,
                                         float& xo, float& lo, float& uo) {
    // p = clip(u - (|l|+|u|)/2, l, u)
    float p = u - 0.5f * (fabsf(l) + fabsf(u));
    p = fminf(fmaxf(p, l), u);

    float sl = spu_f(l);
    float su = spu_f(u);

    // tangent at p, sharing one tanh
    float tp = tanh_half(p);
    bool  ppos = (p >= 0.0f);
    float sp        = ppos ? fmaf(p, p, -0.5f) : fmaf(-0.5f, tp, -0.5f);
    float tan_slope = ppos ? (2.0f * p)        : fmaf(0.25f * tp, tp, -0.25f);
    float tan_int   = sp - p * tan_slope;

    // chord through (l, sl), (u, su)
    float du = (u != l) ? (u - l) : 1.0f;
    float chord_slope = __fdividef(su - sl, du);
    float chord_int   = sl - chord_slope * l;

    // line through (l, sl) and (0, -0.5)
    float dl = (l != 0.0f) ? (-l) : 1.0f;
    float zl_slope = __fdividef(-0.5f - sl, dl);

    bool upos = (u > 0.0f);

    float lb_slope = upos ? (ppos ? tan_slope : zl_slope) : chord_slope;
    float lb_int   = upos ? (ppos ? tan_int   : -0.5f   ) : chord_int;
    float ub_slope = upos ? chord_slope : tan_slope;
    float ub_int   = upos ? chord_int   : tan_int;

    lo = fmaf((lb_slope > 0.0f) ? l : u, lb_slope, lb_int);
    uo = fmaf((ub_slope > 0.0f) ? u : l, ub_slope, ub_int);
    xo = spu_f(x);
}

__global__ __launch_bounds__(256)
void spu_transformer_kernel(const float4* __restrict__ x,
                            const float4* __restrict__ l,
                            const float4* __restrict__ u,
                            float4* __restrict__ x_out,
                            float4* __restrict__ l_out,
                            float4* __restrict__ u_out,
                            int n4) {
    int i = blockIdx.x * blockDim.x + threadIdx.x;
    if (i >= n4) return;

    float4 xv = x[i];
    float4 lv = l[i];
    float4 uv = u[i];

    float4 xo, lo, uo;
    spu_elem(xv.x, lv.x, uv.x, xo.x, lo.x, uo.x);
    spu_elem(xv.y, lv.y, uv.y, xo.y, lo.y, uo.y);
    spu_elem(xv.z, lv.z, uv.z, xo.z, lo.z, uo.z);
    spu_elem(xv.w, lv.w, uv.w, xo.w, lo.w, uo.w);

    x_out[i] = xo;
    l_out[i] = lo;
    u_out[i] = uo;
}

extern "C" void kernel_launch(void* const* d_in, const int* in_sizes, int n_in,
                              void* d_out, int out_size) {
    const float* x = (const float*)d_in[0];
    const float* l = (const float*)d_in[1];
    const float* u = (const float*)d_in[2];
    float* out = (float*)d_out;

    int n = in_sizes[0];            // 16,777,216
    int n4 = n >> 2;                // divisible by 4

    float* x_out = out;
    float* l_out = out + (size_t)n;
    float* u_out = out + 2 * (size_t)n;

    int threads = 256;
    int blocks = (n4 + threads - 1) / threads;   // 16384
    spu_transformer_kernel<<<blocks, threads>>>(
        (const float4*)x, (const float4*)l, (const float4*)u,
        (float4*)x_out, (float4*)l_out, (float4*)u_out, n4);
}